// round 11
// baseline (speedup 1.0000x reference)
#include <cuda_runtime.h>
#include <cstdint>

#define NTOK 4096
#define CDIM 32
#define MAXB 2
#define NTILES 32              // 128-row tiles
#define NIB 16                 // 256-row i-blocks
#define P1BLOCKS 272           // sum over Jt of (Jt/2 + 1)
#define ISPLIT2 8
#define L2E  1.44269504f
#define CSH  57.70780163f      // 40 * log2(e): fixed softmax shift (no max pass)

typedef unsigned int u32;
typedef unsigned long long u64;

// ---------------- static device scratch (no allocations allowed) -----------
__device__ u32   g_p[MAXB * NTOK * (NTOK / 2)];       // P=exp(S-40), bf16 pairs, full matrix
__device__ float g_y[MAXB * NTOK * CDIM];             // Y = x / Z
__device__ float g_zpF[NTILES][MAXB * NTOK];          // forward Z partials (slot = Jt)
__device__ float g_zpT[NIB][MAXB * NTOK];             // transpose Z partials (slot = Ib)
__device__ float g_diag[MAXB * NTOK];                 // exact fp32 diagonal w
__device__ float g_po[ISPLIT2][MAXB * NTOK * CDIM];   // pass2 output partials

// ---------------- packed f32x2 helpers -------------------------------------
__device__ __forceinline__ u64 ffma2(u64 a, u64 b, u64 c) {
    u64 d;
    asm("fma.rn.f32x2 %0, %1, %2, %3;" : "=l"(d) : "l"(a), "l"(b), "l"(c));
    return d;
}
__device__ __forceinline__ u64 addf2(u64 a, u64 b) {
    u64 d;
    asm("add.rn.f32x2 %0, %1, %2;" : "=l"(d) : "l"(a), "l"(b));
    return d;
}
__device__ __forceinline__ float2 unpack2(u64 v) {
    float2 r;
    asm("mov.b64 {%0, %1}, %2;" : "=f"(r.x), "=f"(r.y) : "l"(v));
    return r;
}
__device__ __forceinline__ u64 pack2(float lo, float hi) {
    u64 v;
    asm("mov.b64 %0, {%1, %2};" : "=l"(v) : "f"(lo), "f"(hi));
    return v;
}
__device__ __forceinline__ float ex2f(float x) {
    float y; asm("ex2.approx.ftz.f32 %0, %1;" : "=f"(y) : "f"(x)); return y;
}
__device__ __forceinline__ u32 cvt_bf16x2(float lo, float hi) {
    u32 r;
    asm("cvt.rn.bf16x2.f32 %0, %1, %2;" : "=r"(r) : "f"(hi), "f"(lo));
    return r;  // low half = lo, high half = hi
}
__device__ __forceinline__ float bf_lo(u32 v) { return __uint_as_float(v << 16); }
__device__ __forceinline__ float bf_hi(u32 v) { return __uint_as_float(v & 0xffff0000u); }

// ---------------------------------------------------------------------------
// Pass 1 (R8-identical): block = (Ib, Jt) with 2*Ib <= Jt. Thread owns 2 i-rows.
// Writes forward tiles AND transpose tiles (uint4), Z partials both sides.
// ---------------------------------------------------------------------------
__global__ void __launch_bounds__(128, 4)
p1_kernel(const float* __restrict__ x) {
    __shared__ float sy[32][32];        // X_j sub-tile (4KB)
    __shared__ u32 swA[128][17];        // w bf16-pairs for sub-tile A
    __shared__ u32 swB[128][17];        // for sub-tile B
    __shared__ float szp[32][4];        // per-jrow column-Z partials (A+B merged)

    const int tid = threadIdx.x;
    const int bb  = blockIdx.y;

    int q = blockIdx.x, Jt = 0;
    while (q >= (Jt / 2 + 1)) { q -= Jt / 2 + 1; Jt++; }
    const int Ib  = q;
    const int ItA = 2 * Ib;
    const int ItB = 2 * Ib + 1;
    const bool tB  = (Jt > ItA);
    const bool tBB = (Jt > ItB);

    const float* xb = x + (size_t)bb * NTOK * CDIM;
    const int rowA = ItA * 128 + tid;
    const int rowB = ItB * 128 + tid;

    u64 rxA[16], rxB[16];
    {
        const ulonglong2* pa = reinterpret_cast<const ulonglong2*>(xb + (size_t)rowA * CDIM);
        const ulonglong2* pb = reinterpret_cast<const ulonglong2*>(xb + (size_t)rowB * CDIM);
#pragma unroll
        for (int k = 0; k < 8; k++) {
            ulonglong2 va = pa[k]; rxA[2*k] = va.x; rxA[2*k+1] = va.y;
            ulonglong2 vb = pb[k]; rxB[2*k] = vb.x; rxB[2*k+1] = vb.y;
        }
    }

    float ZiA = 0.f, ZiB = 0.f;

#pragma unroll 1
    for (int jt = 0; jt < 4; jt++) {
        const int jr0 = Jt * 128 + jt * 32;
        __syncthreads();
        {
            const float4* gs = reinterpret_cast<const float4*>(xb + (size_t)jr0 * CDIM);
            float4* sd = reinterpret_cast<float4*>(&sy[0][0]);
            sd[tid] = gs[tid]; sd[tid + 128] = gs[tid + 128];
        }
        __syncthreads();

#pragma unroll
        for (int p = 0; p < 16; p++) {
            float wvA[2], wvB[2];
#pragma unroll
            for (int h = 0; h < 2; h++) {
                const ulonglong2* qq = reinterpret_cast<const ulonglong2*>(&sy[2*p + h][0]);
                u64 eA = 0, oA = 0, eB = 0, oB = 0;
#pragma unroll
                for (int k = 0; k < 4; k++) {
                    ulonglong2 v0 = qq[2*k];        // shared j-row data
                    ulonglong2 v1 = qq[2*k + 1];
                    eA = ffma2(v0.x, rxA[4*k],     eA);
                    oA = ffma2(v0.y, rxA[4*k + 1], oA);
                    eA = ffma2(v1.x, rxA[4*k + 2], eA);
                    oA = ffma2(v1.y, rxA[4*k + 3], oA);
                    eB = ffma2(v0.x, rxB[4*k],     eB);
                    oB = ffma2(v0.y, rxB[4*k + 1], oB);
                    eB = ffma2(v1.x, rxB[4*k + 2], eB);
                    oB = ffma2(v1.y, rxB[4*k + 3], oB);
                }
                float2 fA = unpack2(addf2(eA, oA));
                float2 fB = unpack2(addf2(eB, oB));
                float sA = fA.x + fA.y;
                float sB = fB.x + fB.y;
                float wA = ex2f(fmaf(sA, L2E, -CSH));
                float wB = ex2f(fmaf(sB, L2E, -CSH));
                ZiA += wA; ZiB += wB;
                const int jglob = jr0 + 2*p + h;
                if (jglob == rowA) g_diag[bb * NTOK + rowA] = wA;  // exact diagonal
                if (tB && jglob == rowB) g_diag[bb * NTOK + rowB] = wB;
                wvA[h] = wA; wvB[h] = wB;
            }
            swA[tid][p] = cvt_bf16x2(wvA[0], wvA[1]);
            swB[tid][p] = cvt_bf16x2(wvB[0], wvB[1]);
        }
        __syncthreads();

        // forward writes: 4 x STG.128 per thread per sub-tile
#pragma unroll
        for (int u = 0; u < 4; u++) {
            int v = tid + u * 128;
            int row = v >> 2, c4 = (v & 3) * 4;
            uint4 w4 = make_uint4(swA[row][c4], swA[row][c4 + 1],
                                  swA[row][c4 + 2], swA[row][c4 + 3]);
            *reinterpret_cast<uint4*>(
                &g_p[((size_t)(bb * NTOK + ItA * 128 + row)) * (NTOK / 2) + (jr0 >> 1) + c4])
                = w4;
            if (tB) {
                uint4 w4b = make_uint4(swB[row][c4], swB[row][c4 + 1],
                                       swB[row][c4 + 2], swB[row][c4 + 3]);
                *reinterpret_cast<uint4*>(
                    &g_p[((size_t)(bb * NTOK + ItB * 128 + row)) * (NTOK / 2) + (jr0 >> 1) + c4])
                    = w4b;
            }
        }

        if (tB) {
            // transpose writes: rows jr0..jr0+31, cols = i of ItA (+ItB), uint4
            const int jr = tid >> 2;          // 0..31
            const int qd = tid & 3;           // quarter of the 64 u32 cols
            const int jpair = jr >> 1;
            const u32 sel = (jr & 1) ? 0x7632u : 0x5410u;
            float zj = 0.f;
            u32* dstA = &g_p[((size_t)(bb * NTOK + jr0 + jr)) * (NTOK / 2) + ItA * 64 + qd * 16];
#pragma unroll
            for (int g4 = 0; g4 < 4; g4++) {
                u32 o0 = __byte_perm(swA[2*(qd*16 + 4*g4)    ][jpair], swA[2*(qd*16 + 4*g4)     + 1][jpair], sel);
                u32 o1 = __byte_perm(swA[2*(qd*16 + 4*g4 + 1)][jpair], swA[2*(qd*16 + 4*g4 + 1) + 1][jpair], sel);
                u32 o2 = __byte_perm(swA[2*(qd*16 + 4*g4 + 2)][jpair], swA[2*(qd*16 + 4*g4 + 2) + 1][jpair], sel);
                u32 o3 = __byte_perm(swA[2*(qd*16 + 4*g4 + 3)][jpair], swA[2*(qd*16 + 4*g4 + 3) + 1][jpair], sel);
                *reinterpret_cast<uint4*>(dstA + 4*g4) = make_uint4(o0, o1, o2, o3);
                zj += __uint_as_float(o0 << 16) + __uint_as_float(o0 & 0xffff0000u)
                    + __uint_as_float(o1 << 16) + __uint_as_float(o1 & 0xffff0000u)
                    + __uint_as_float(o2 << 16) + __uint_as_float(o2 & 0xffff0000u)
                    + __uint_as_float(o3 << 16) + __uint_as_float(o3 & 0xffff0000u);
            }
            if (tBB) {
                u32* dstB = &g_p[((size_t)(bb * NTOK + jr0 + jr)) * (NTOK / 2) + ItB * 64 + qd * 16];
#pragma unroll
                for (int g4 = 0; g4 < 4; g4++) {
                    u32 o0 = __byte_perm(swB[2*(qd*16 + 4*g4)    ][jpair], swB[2*(qd*16 + 4*g4)     + 1][jpair], sel);
                    u32 o1 = __byte_perm(swB[2*(qd*16 + 4*g4 + 1)][jpair], swB[2*(qd*16 + 4*g4 + 1) + 1][jpair], sel);
                    u32 o2 = __byte_perm(swB[2*(qd*16 + 4*g4 + 2)][jpair], swB[2*(qd*16 + 4*g4 + 2) + 1][jpair], sel);
                    u32 o3 = __byte_perm(swB[2*(qd*16 + 4*g4 + 3)][jpair], swB[2*(qd*16 + 4*g4 + 3) + 1][jpair], sel);
                    *reinterpret_cast<uint4*>(dstB + 4*g4) = make_uint4(o0, o1, o2, o3);
                    zj += __uint_as_float(o0 << 16) + __uint_as_float(o0 & 0xffff0000u)
                        + __uint_as_float(o1 << 16) + __uint_as_float(o1 & 0xffff0000u)
                        + __uint_as_float(o2 << 16) + __uint_as_float(o2 & 0xffff0000u)
                        + __uint_as_float(o3 << 16) + __uint_as_float(o3 & 0xffff0000u);
                }
            }
            szp[jr][qd] = zj;
        }
        __syncthreads();
        if (tB && tid < 32) {
            g_zpT[Ib][bb * NTOK + jr0 + tid] =
                szp[tid][0] + szp[tid][1] + szp[tid][2] + szp[tid][3];
        }
    }

    g_zpF[Jt][bb * NTOK + rowA] = ZiA;
    if (tB) g_zpF[Jt][bb * NTOK + rowB] = ZiB;
}

// ---------------------------------------------------------------------------
// ky: Y = x / Z  (Z = 32 forward + 16 transpose partial slots)
// ---------------------------------------------------------------------------
__global__ void ky_kernel(const float* __restrict__ x, int nrow) {
    int r = blockIdx.x * 128 + threadIdx.x;
    if (r >= nrow) return;
    float Z = 0.f;
#pragma unroll
    for (int s = 0; s < NTILES; s++) Z += g_zpF[s][r];
#pragma unroll
    for (int s = 0; s < NIB; s++) Z += g_zpT[s][r];
    float inv = 1.0f / Z;
    const float4* xs = reinterpret_cast<const float4*>(x + (size_t)r * CDIM);
    float4* yd = reinterpret_cast<float4*>(g_y + (size_t)r * CDIM);
#pragma unroll
    for (int q = 0; q < 8; q++) {
        float4 v = xs[q];
        v.x *= inv; v.y *= inv; v.z *= inv; v.w *= inv;
        yd[q] = v;
    }
}

// ---------------------------------------------------------------------------
// Pass 2 (row mode only, full P): out_partial[j] = sum_{i in isp chunk} P[j][i]*Y[i]
// grid(16, ISPLIT2=8, b), 256 threads. Thread = (jpl = tid>>1, h = tid&1):
//   owns j-pair j0=2*(jc*128+jpl), j1=j0+1, channels [h*16, h*16+16).
// Per 32-i sub-tile: 8 x LDG.128 of P rows, Y from smem.
// ---------------------------------------------------------------------------
__global__ void __launch_bounds__(256, 2)
p2_kernel() {
    __shared__ float sy[32][32];        // Y tile (4KB)

    const int tid = threadIdx.x;
    const int h   = tid & 1;
    const int jpl = tid >> 1;           // 0..127
    const int jc  = blockIdx.x;         // 0..15
    const int isp = blockIdx.y;         // 0..7
    const int bb  = blockIdx.z;

    const int jp   = jc * 128 + jpl;    // global j-pair index
    const int j0   = 2 * jp;
    const size_t row0  = (size_t)(bb * NTOK) + j0;
    const size_t prow0 = row0 * (NTOK / 2);
    const size_t prow1 = (row0 + 1) * (NTOK / 2);

    u64 acc0[8], acc1[8];
#pragma unroll
    for (int k = 0; k < 8; k++) { acc0[k] = 0ull; acc1[k] = 0ull; }

#pragma unroll 1
    for (int sub = 0; sub < 16; sub++) {
        const int i0 = isp * 512 + sub * 32;
        __syncthreads();
        reinterpret_cast<float4*>(&sy[0][0])[tid] =
            reinterpret_cast<const float4*>(g_y + (size_t)(bb * NTOK + i0) * CDIM)[tid];
        __syncthreads();

#pragma unroll
        for (int half = 0; half < 2; half++) {
            const size_t off = (size_t)(i0 >> 1) + half * 8;
            uint4 a0 = *reinterpret_cast<const uint4*>(&g_p[prow0 + off]);
            uint4 a1 = *reinterpret_cast<const uint4*>(&g_p[prow0 + off + 4]);
            uint4 b0 = *reinterpret_cast<const uint4*>(&g_p[prow1 + off]);
            uint4 b1 = *reinterpret_cast<const uint4*>(&g_p[prow1 + off + 4]);
            u32 pa[8] = {a0.x, a0.y, a0.z, a0.w, a1.x, a1.y, a1.z, a1.w};
            u32 pb[8] = {b0.x, b0.y, b0.z, b0.w, b1.x, b1.y, b1.z, b1.w};
#pragma unroll
            for (int p = 0; p < 8; p++) {
                const int iy = 2 * (half * 8 + p);
                u32 pk0 = pa[p], pk1 = pb[p];
                u64 w00 = pack2(bf_lo(pk0), bf_lo(pk0)); // i=iy,   j0
                u64 w01 = pack2(bf_hi(pk0), bf_hi(pk0)); // i=iy+1, j0
                u64 w10 = pack2(bf_lo(pk1), bf_lo(pk1)); // i=iy,   j1
                u64 w11 = pack2(bf_hi(pk1), bf_hi(pk1)); // i=iy+1, j1
                const ulonglong2* ya = reinterpret_cast<const ulonglong2*>(&sy[iy][h * 16]);
                const ulonglong2* yb = reinterpret_cast<const ulonglong2*>(&sy[iy + 1][h * 16]);
#pragma unroll
                for (int k = 0; k < 4; k++) {
                    ulonglong2 va = ya[k];
                    acc0[2*k]     = ffma2(w00, va.x, acc0[2*k]);
                    acc0[2*k + 1] = ffma2(w00, va.y, acc0[2*k + 1]);
                    acc1[2*k]     = ffma2(w10, va.x, acc1[2*k]);
                    acc1[2*k + 1] = ffma2(w10, va.y, acc1[2*k + 1]);
                }
#pragma unroll
                for (int k = 0; k < 4; k++) {
                    ulonglong2 vb = yb[k];
                    acc0[2*k]     = ffma2(w01, vb.x, acc0[2*k]);
                    acc0[2*k + 1] = ffma2(w01, vb.y, acc0[2*k + 1]);
                    acc1[2*k]     = ffma2(w11, vb.x, acc1[2*k]);
                    acc1[2*k + 1] = ffma2(w11, vb.y, acc1[2*k + 1]);
                }
            }
        }
    }

    // diagonal bf16-rounding correction (the isp chunk containing i == j)
    if ((j0 >> 9) == isp) {
        float wex0 = g_diag[row0];
        u32 pk0 = g_p[prow0 + jp];                  // P[j0][j0] in lo half
        float d0 = wex0 - bf_lo(pk0);
        u64 dp0 = pack2(d0, d0);
        const ulonglong2* y0 =
            reinterpret_cast<const ulonglong2*>(g_y + row0 * CDIM + h * 16);
#pragma unroll
        for (int k = 0; k < 4; k++) {
            ulonglong2 v = y0[k];
            acc0[2*k]     = ffma2(dp0, v.x, acc0[2*k]);
            acc0[2*k + 1] = ffma2(dp0, v.y, acc0[2*k + 1]);
        }
        float wex1 = g_diag[row0 + 1];
        u32 pk1 = g_p[prow1 + jp];                  // P[j1][j1] in hi half
        float d1 = wex1 - bf_hi(pk1);
        u64 dp1 = pack2(d1, d1);
        const ulonglong2* y1 =
            reinterpret_cast<const ulonglong2*>(g_y + (row0 + 1) * CDIM + h * 16);
#pragma unroll
        for (int k = 0; k < 4; k++) {
            ulonglong2 v = y1[k];
            acc1[2*k]     = ffma2(dp1, v.x, acc1[2*k]);
            acc1[2*k + 1] = ffma2(dp1, v.y, acc1[2*k + 1]);
        }
    }

    {
        ulonglong2* d0 = reinterpret_cast<ulonglong2*>(
            &g_po[isp][row0 * CDIM + h * 16]);
        ulonglong2* d1 = reinterpret_cast<ulonglong2*>(
            &g_po[isp][(row0 + 1) * CDIM + h * 16]);
#pragma unroll
        for (int k = 0; k < 4; k++) {
            ulonglong2 v0; v0.x = acc0[2*k]; v0.y = acc0[2*k + 1];
            d0[k] = v0;
            ulonglong2 v1; v1.x = acc1[2*k]; v1.y = acc1[2*k + 1];
            d1[k] = v1;
        }
    }
}

// ---------------------------------------------------------------------------
// k3: out = (sum of 8 partials) * gamma + x
// ---------------------------------------------------------------------------
__global__ void k3_kernel(const float* __restrict__ x, const float* __restrict__ gamma,
                          float* __restrict__ out, int n4) {
    int i = blockIdx.x * 256 + threadIdx.x;
    if (i >= n4) return;
    float g = gamma[0];
    float4 s = reinterpret_cast<const float4*>(g_po[0])[i];
#pragma unroll
    for (int p = 1; p < ISPLIT2; p++) {
        float4 v = reinterpret_cast<const float4*>(g_po[p])[i];
        s.x += v.x; s.y += v.y; s.z += v.z; s.w += v.w;
    }
    float4 xi = reinterpret_cast<const float4*>(x)[i];
    float4 o;
    o.x = fmaf(s.x, g, xi.x);
    o.y = fmaf(s.y, g, xi.y);
    o.z = fmaf(s.z, g, xi.z);
    o.w = fmaf(s.w, g, xi.w);
    reinterpret_cast<float4*>(out)[i] = o;
}

extern "C" void kernel_launch(void* const* d_in, const int* in_sizes, int n_in,
                              void* d_out, int out_size) {
    const float* x     = (const float*)d_in[0];
    const float* gamma = (const float*)d_in[1];
    float* out = (float*)d_out;

    int b = in_sizes[0] / (NTOK * CDIM);
    if (b < 1) b = 1;
    if (b > MAXB) b = MAXB;
    int nrow = b * NTOK;

    {
        dim3 g(P1BLOCKS, b);
        p1_kernel<<<g, 128>>>(x);
    }
    ky_kernel<<<(nrow + 127) / 128, 128>>>(x, nrow);
    {
        dim3 g(16, ISPLIT2, b);
        p2_kernel<<<g, 256>>>();
    }
    int n4 = nrow * CDIM / 4;
    k3_kernel<<<(n4 + 255) / 256, 256>>>(x, gamma, out, n4);
}

// round 12
// speedup vs baseline: 1.0515x; 1.0515x over previous
#include <cuda_runtime.h>
#include <cstdint>

#define NTOK 4096
#define CDIM 32
#define MAXB 2
#define NTILES 32              // 128-row tiles
#define NIB 16                 // 256-row i-blocks
#define P1BLOCKS 272           // sum over Jt of (Jt/2 + 1)
#define ISPLIT2 16
#define L2E  1.44269504f
#define CSH  57.70780163f      // 40 * log2(e): fixed softmax shift (no max pass)

typedef unsigned int u32;
typedef unsigned long long u64;

// ---------------- static device scratch (no allocations allowed) -----------
__device__ u32   g_p[MAXB * NTOK * (NTOK / 2)];       // P=exp(S-40), bf16 pairs, full matrix
__device__ float g_y[MAXB * NTOK * CDIM];             // Y = x / Z
__device__ float g_zpF[NTILES][MAXB * NTOK];          // forward Z partials (slot = Jt)
__device__ float g_zpT[NIB][MAXB * NTOK];             // transpose Z partials (slot = Ib)
__device__ float g_diag[MAXB * NTOK];                 // exact fp32 diagonal w
__device__ float g_po[ISPLIT2][MAXB * NTOK * CDIM];   // pass2 output partials

// ---------------- packed f32x2 helpers -------------------------------------
__device__ __forceinline__ u64 ffma2(u64 a, u64 b, u64 c) {
    u64 d;
    asm("fma.rn.f32x2 %0, %1, %2, %3;" : "=l"(d) : "l"(a), "l"(b), "l"(c));
    return d;
}
__device__ __forceinline__ u64 addf2(u64 a, u64 b) {
    u64 d;
    asm("add.rn.f32x2 %0, %1, %2;" : "=l"(d) : "l"(a), "l"(b));
    return d;
}
__device__ __forceinline__ float2 unpack2(u64 v) {
    float2 r;
    asm("mov.b64 {%0, %1}, %2;" : "=f"(r.x), "=f"(r.y) : "l"(v));
    return r;
}
__device__ __forceinline__ u64 pack2(float lo, float hi) {
    u64 v;
    asm("mov.b64 %0, {%1, %2};" : "=l"(v) : "f"(lo), "f"(hi));
    return v;
}
__device__ __forceinline__ float ex2f(float x) {
    float y; asm("ex2.approx.ftz.f32 %0, %1;" : "=f"(y) : "f"(x)); return y;
}
__device__ __forceinline__ u32 cvt_bf16x2(float lo, float hi) {
    u32 r;
    asm("cvt.rn.bf16x2.f32 %0, %1, %2;" : "=r"(r) : "f"(hi), "f"(lo));
    return r;  // low half = lo, high half = hi
}
__device__ __forceinline__ float bf_lo(u32 v) { return __uint_as_float(v << 16); }
__device__ __forceinline__ float bf_hi(u32 v) { return __uint_as_float(v & 0xffff0000u); }

// ---------------------------------------------------------------------------
// Pass 1 (R8 + split-Z chains): block = (Ib, Jt) with 2*Ib <= Jt.
// Thread owns 2 i-rows; forward + transpose tile stores (uint4).
// ---------------------------------------------------------------------------
__global__ void __launch_bounds__(128, 4)
p1_kernel(const float* __restrict__ x) {
    __shared__ float sy[32][32];        // X_j sub-tile (4KB)
    __shared__ u32 swA[128][17];        // w bf16-pairs for sub-tile A
    __shared__ u32 swB[128][17];        // for sub-tile B
    __shared__ float szp[32][4];        // per-jrow column-Z partials (A+B merged)

    const int tid = threadIdx.x;
    const int bb  = blockIdx.y;

    int q = blockIdx.x, Jt = 0;
    while (q >= (Jt / 2 + 1)) { q -= Jt / 2 + 1; Jt++; }
    const int Ib  = q;
    const int ItA = 2 * Ib;
    const int ItB = 2 * Ib + 1;
    const bool tB  = (Jt > ItA);
    const bool tBB = (Jt > ItB);

    const float* xb = x + (size_t)bb * NTOK * CDIM;
    const int rowA = ItA * 128 + tid;
    const int rowB = ItB * 128 + tid;

    u64 rxA[16], rxB[16];
    {
        const ulonglong2* pa = reinterpret_cast<const ulonglong2*>(xb + (size_t)rowA * CDIM);
        const ulonglong2* pb = reinterpret_cast<const ulonglong2*>(xb + (size_t)rowB * CDIM);
#pragma unroll
        for (int k = 0; k < 8; k++) {
            ulonglong2 va = pa[k]; rxA[2*k] = va.x; rxA[2*k+1] = va.y;
            ulonglong2 vb = pb[k]; rxB[2*k] = vb.x; rxB[2*k+1] = vb.y;
        }
    }

    float ZiA0 = 0.f, ZiA1 = 0.f, ZiB0 = 0.f, ZiB1 = 0.f;

#pragma unroll 1
    for (int jt = 0; jt < 4; jt++) {
        const int jr0 = Jt * 128 + jt * 32;
        __syncthreads();
        {
            const float4* gs = reinterpret_cast<const float4*>(xb + (size_t)jr0 * CDIM);
            float4* sd = reinterpret_cast<float4*>(&sy[0][0]);
            sd[tid] = gs[tid]; sd[tid + 128] = gs[tid + 128];
        }
        __syncthreads();

#pragma unroll
        for (int p = 0; p < 16; p++) {
            float wvA[2], wvB[2];
#pragma unroll
            for (int h = 0; h < 2; h++) {
                const ulonglong2* qq = reinterpret_cast<const ulonglong2*>(&sy[2*p + h][0]);
                u64 eA = 0, oA = 0, eB = 0, oB = 0;
#pragma unroll
                for (int k = 0; k < 4; k++) {
                    ulonglong2 v0 = qq[2*k];        // shared j-row data
                    ulonglong2 v1 = qq[2*k + 1];
                    eA = ffma2(v0.x, rxA[4*k],     eA);
                    oA = ffma2(v0.y, rxA[4*k + 1], oA);
                    eA = ffma2(v1.x, rxA[4*k + 2], eA);
                    oA = ffma2(v1.y, rxA[4*k + 3], oA);
                    eB = ffma2(v0.x, rxB[4*k],     eB);
                    oB = ffma2(v0.y, rxB[4*k + 1], oB);
                    eB = ffma2(v1.x, rxB[4*k + 2], eB);
                    oB = ffma2(v1.y, rxB[4*k + 3], oB);
                }
                float2 fA = unpack2(addf2(eA, oA));
                float2 fB = unpack2(addf2(eB, oB));
                float sA = fA.x + fA.y;
                float sB = fB.x + fB.y;
                float wA = ex2f(fmaf(sA, L2E, -CSH));
                float wB = ex2f(fmaf(sB, L2E, -CSH));
                if (h) { ZiA1 += wA; ZiB1 += wB; }
                else   { ZiA0 += wA; ZiB0 += wB; }
                const int jglob = jr0 + 2*p + h;
                if (jglob == rowA) g_diag[bb * NTOK + rowA] = wA;  // exact diagonal
                if (tB && jglob == rowB) g_diag[bb * NTOK + rowB] = wB;
                wvA[h] = wA; wvB[h] = wB;
            }
            swA[tid][p] = cvt_bf16x2(wvA[0], wvA[1]);
            swB[tid][p] = cvt_bf16x2(wvB[0], wvB[1]);
        }
        __syncthreads();

        // forward writes: 4 x STG.128 per thread per sub-tile
#pragma unroll
        for (int u = 0; u < 4; u++) {
            int v = tid + u * 128;
            int row = v >> 2, c4 = (v & 3) * 4;
            uint4 w4 = make_uint4(swA[row][c4], swA[row][c4 + 1],
                                  swA[row][c4 + 2], swA[row][c4 + 3]);
            *reinterpret_cast<uint4*>(
                &g_p[((size_t)(bb * NTOK + ItA * 128 + row)) * (NTOK / 2) + (jr0 >> 1) + c4])
                = w4;
            if (tB) {
                uint4 w4b = make_uint4(swB[row][c4], swB[row][c4 + 1],
                                       swB[row][c4 + 2], swB[row][c4 + 3]);
                *reinterpret_cast<uint4*>(
                    &g_p[((size_t)(bb * NTOK + ItB * 128 + row)) * (NTOK / 2) + (jr0 >> 1) + c4])
                    = w4b;
            }
        }

        if (tB) {
            // transpose writes: rows jr0..jr0+31, cols = i of ItA (+ItB), uint4
            const int jr = tid >> 2;          // 0..31
            const int qd = tid & 3;           // quarter of the 64 u32 cols
            const int jpair = jr >> 1;
            const u32 sel = (jr & 1) ? 0x7632u : 0x5410u;
            float zj = 0.f;
            u32* dstA = &g_p[((size_t)(bb * NTOK + jr0 + jr)) * (NTOK / 2) + ItA * 64 + qd * 16];
#pragma unroll
            for (int g4 = 0; g4 < 4; g4++) {
                u32 o0 = __byte_perm(swA[2*(qd*16 + 4*g4)    ][jpair], swA[2*(qd*16 + 4*g4)     + 1][jpair], sel);
                u32 o1 = __byte_perm(swA[2*(qd*16 + 4*g4 + 1)][jpair], swA[2*(qd*16 + 4*g4 + 1) + 1][jpair], sel);
                u32 o2 = __byte_perm(swA[2*(qd*16 + 4*g4 + 2)][jpair], swA[2*(qd*16 + 4*g4 + 2) + 1][jpair], sel);
                u32 o3 = __byte_perm(swA[2*(qd*16 + 4*g4 + 3)][jpair], swA[2*(qd*16 + 4*g4 + 3) + 1][jpair], sel);
                *reinterpret_cast<uint4*>(dstA + 4*g4) = make_uint4(o0, o1, o2, o3);
                zj += __uint_as_float(o0 << 16) + __uint_as_float(o0 & 0xffff0000u)
                    + __uint_as_float(o1 << 16) + __uint_as_float(o1 & 0xffff0000u)
                    + __uint_as_float(o2 << 16) + __uint_as_float(o2 & 0xffff0000u)
                    + __uint_as_float(o3 << 16) + __uint_as_float(o3 & 0xffff0000u);
            }
            if (tBB) {
                u32* dstB = &g_p[((size_t)(bb * NTOK + jr0 + jr)) * (NTOK / 2) + ItB * 64 + qd * 16];
#pragma unroll
                for (int g4 = 0; g4 < 4; g4++) {
                    u32 o0 = __byte_perm(swB[2*(qd*16 + 4*g4)    ][jpair], swB[2*(qd*16 + 4*g4)     + 1][jpair], sel);
                    u32 o1 = __byte_perm(swB[2*(qd*16 + 4*g4 + 1)][jpair], swB[2*(qd*16 + 4*g4 + 1) + 1][jpair], sel);
                    u32 o2 = __byte_perm(swB[2*(qd*16 + 4*g4 + 2)][jpair], swB[2*(qd*16 + 4*g4 + 2) + 1][jpair], sel);
                    u32 o3 = __byte_perm(swB[2*(qd*16 + 4*g4 + 3)][jpair], swB[2*(qd*16 + 4*g4 + 3) + 1][jpair], sel);
                    *reinterpret_cast<uint4*>(dstB + 4*g4) = make_uint4(o0, o1, o2, o3);
                    zj += __uint_as_float(o0 << 16) + __uint_as_float(o0 & 0xffff0000u)
                        + __uint_as_float(o1 << 16) + __uint_as_float(o1 & 0xffff0000u)
                        + __uint_as_float(o2 << 16) + __uint_as_float(o2 & 0xffff0000u)
                        + __uint_as_float(o3 << 16) + __uint_as_float(o3 & 0xffff0000u);
                }
            }
            szp[jr][qd] = zj;
        }
        __syncthreads();
        if (tB && tid < 32) {
            g_zpT[Ib][bb * NTOK + jr0 + tid] =
                szp[tid][0] + szp[tid][1] + szp[tid][2] + szp[tid][3];
        }
    }

    g_zpF[Jt][bb * NTOK + rowA] = ZiA0 + ZiA1;
    if (tB) g_zpF[Jt][bb * NTOK + rowB] = ZiB0 + ZiB1;
}

// ---------------------------------------------------------------------------
// ky: Y = x / Z  (Z = 32 forward + 16 transpose partial slots)
// 4 independent accumulator chains for MLP.
// ---------------------------------------------------------------------------
__global__ void ky_kernel(const float* __restrict__ x, int nrow) {
    int r = blockIdx.x * 128 + threadIdx.x;
    if (r >= nrow) return;
    float Z0 = 0.f, Z1 = 0.f, Z2 = 0.f, Z3 = 0.f;
#pragma unroll
    for (int s = 0; s < NTILES; s += 4) {
        Z0 += g_zpF[s][r];
        Z1 += g_zpF[s + 1][r];
        Z2 += g_zpF[s + 2][r];
        Z3 += g_zpF[s + 3][r];
    }
#pragma unroll
    for (int s = 0; s < NIB; s += 4) {
        Z0 += g_zpT[s][r];
        Z1 += g_zpT[s + 1][r];
        Z2 += g_zpT[s + 2][r];
        Z3 += g_zpT[s + 3][r];
    }
    float inv = 1.0f / ((Z0 + Z1) + (Z2 + Z3));
    const float4* xs = reinterpret_cast<const float4*>(x + (size_t)r * CDIM);
    float4* yd = reinterpret_cast<float4*>(g_y + (size_t)r * CDIM);
#pragma unroll
    for (int q = 0; q < 8; q++) {
        float4 v = xs[q];
        v.x *= inv; v.y *= inv; v.z *= inv; v.w *= inv;
        yd[q] = v;
    }
}

// ---------------------------------------------------------------------------
// Pass 2 (R8-identical): out_partial[j] = sum_{i in isp range} P[j][i] * Y[i]
// grid(8, 16, b), 256 threads. Thread = (jg = tid>>1, h = tid&1):
//   owns 4 j-rows {jb*512 + r*128 + jg} x 16 channels (half h).
// ---------------------------------------------------------------------------
__global__ void __launch_bounds__(256, 2)
p2_kernel() {
    __shared__ float sy[32][32];        // Y tile (4KB)

    const int tid = threadIdx.x;
    const int h   = tid & 1;
    const int jg  = tid >> 1;           // 0..127
    const int jb  = blockIdx.x;         // 0..7
    const int isp = blockIdx.y;         // 0..15
    const int bb  = blockIdx.z;

    u64 acc[4][8];
#pragma unroll
    for (int r = 0; r < 4; r++)
#pragma unroll
        for (int k = 0; k < 8; k++) acc[r][k] = 0ull;

    // row r: j = jb*512 + r*128 + jg
    size_t prow[4];
#pragma unroll
    for (int r = 0; r < 4; r++)
        prow[r] = (size_t)(bb * NTOK + jb * 512 + r * 128 + jg) * (NTOK / 2);

#pragma unroll 1
    for (int it = 0; it < 8; it++) {
        const int i0 = isp * 256 + it * 32;
        __syncthreads();
        {
            const float4* gs = reinterpret_cast<const float4*>(g_y + (size_t)(bb * NTOK + i0) * CDIM);
            reinterpret_cast<float4*>(&sy[0][0])[tid] = gs[tid];
        }
        __syncthreads();

#pragma unroll
        for (int sub = 0; sub < 4; sub++) {
            // P weights for 4 i-pairs x 4 rows
            u32 pr[4][4];
#pragma unroll
            for (int r = 0; r < 4; r++) {
                uint4 v = *reinterpret_cast<const uint4*>(
                    &g_p[prow[r] + (i0 >> 1) + sub * 4]);
                pr[r][0] = v.x; pr[r][1] = v.y; pr[r][2] = v.z; pr[r][3] = v.w;
            }
#pragma unroll
            for (int pp = 0; pp < 4; pp++) {
                const int p = sub * 4 + pp;   // i-pair within tile
                const ulonglong2* q0 = reinterpret_cast<const ulonglong2*>(&sy[2*p][h*16]);
                const ulonglong2* q1 = reinterpret_cast<const ulonglong2*>(&sy[2*p + 1][h*16]);
                u64 y00 = q0[0].x, y01 = q0[0].y, y02 = q0[1].x, y03 = q0[1].y;
                u64 y04 = q0[2].x, y05 = q0[2].y, y06 = q0[3].x, y07 = q0[3].y;
                u64 y10 = q1[0].x, y11 = q1[0].y, y12 = q1[1].x, y13 = q1[1].y;
                u64 y14 = q1[2].x, y15 = q1[2].y, y16 = q1[3].x, y17 = q1[3].y;
#pragma unroll
                for (int r = 0; r < 4; r++) {
                    u32 pk = pr[r][pp];
                    float w0 = __uint_as_float(pk << 16);           // P[j][2p]
                    float w1 = __uint_as_float(pk & 0xffff0000u);   // P[j][2p+1]
                    u64 w0p = pack2(w0, w0);
                    u64 w1p = pack2(w1, w1);
                    acc[r][0] = ffma2(w0p, y00, acc[r][0]);
                    acc[r][1] = ffma2(w0p, y01, acc[r][1]);
                    acc[r][2] = ffma2(w0p, y02, acc[r][2]);
                    acc[r][3] = ffma2(w0p, y03, acc[r][3]);
                    acc[r][4] = ffma2(w0p, y04, acc[r][4]);
                    acc[r][5] = ffma2(w0p, y05, acc[r][5]);
                    acc[r][6] = ffma2(w0p, y06, acc[r][6]);
                    acc[r][7] = ffma2(w0p, y07, acc[r][7]);
                    acc[r][0] = ffma2(w1p, y10, acc[r][0]);
                    acc[r][1] = ffma2(w1p, y11, acc[r][1]);
                    acc[r][2] = ffma2(w1p, y12, acc[r][2]);
                    acc[r][3] = ffma2(w1p, y13, acc[r][3]);
                    acc[r][4] = ffma2(w1p, y14, acc[r][4]);
                    acc[r][5] = ffma2(w1p, y15, acc[r][5]);
                    acc[r][6] = ffma2(w1p, y16, acc[r][6]);
                    acc[r][7] = ffma2(w1p, y17, acc[r][7]);
                }
            }
        }
    }

    // diagonal bf16-rounding correction (isp owning i == j), per owned row
#pragma unroll
    for (int r = 0; r < 4; r++) {
        int j = jb * 512 + r * 128 + jg;
        if ((j >> 8) == isp) {
            int row = bb * NTOK + j;
            float wex = g_diag[row];
            u32 pk = g_p[(size_t)row * (NTOK / 2) + (j >> 1)];
            float wbf = (j & 1) ? bf_hi(pk) : bf_lo(pk);
            float d = wex - wbf;
            u64 dp = pack2(d, d);
            const ulonglong2* yq =
                reinterpret_cast<const ulonglong2*>(g_y + (size_t)row * CDIM + h * 16);
#pragma unroll
            for (int kk = 0; kk < 4; kk++) {
                ulonglong2 v = yq[kk];
                acc[r][2*kk]     = ffma2(dp, v.x, acc[r][2*kk]);
                acc[r][2*kk + 1] = ffma2(dp, v.y, acc[r][2*kk + 1]);
            }
        }
    }

#pragma unroll
    for (int r = 0; r < 4; r++) {
        int j = jb * 512 + r * 128 + jg;
        ulonglong2* dst = reinterpret_cast<ulonglong2*>(
            &g_po[isp][(size_t)(bb * NTOK + j) * CDIM + h * 16]);
#pragma unroll
        for (int k = 0; k < 4; k++) {
            ulonglong2 v;
            v.x = acc[r][2*k];
            v.y = acc[r][2*k + 1];
            dst[k] = v;
        }
    }
}

// ---------------------------------------------------------------------------
// k3: out = (sum of 16 partials) * gamma + x.
// All 16 partial loads batched into registers (MLP), tree reduction.
// ---------------------------------------------------------------------------
__global__ void k3_kernel(const float* __restrict__ x, const float* __restrict__ gamma,
                          float* __restrict__ out, int n4) {
    int i = blockIdx.x * 256 + threadIdx.x;
    if (i >= n4) return;
    float g = gamma[0];
    float4 v[16];
#pragma unroll
    for (int p = 0; p < 16; p++)
        v[p] = reinterpret_cast<const float4*>(g_po[p])[i];
    float4 xi = reinterpret_cast<const float4*>(x)[i];
    // tree reduction: 16 -> 8 -> 4 -> 2 -> 1
#pragma unroll
    for (int st = 8; st >= 1; st >>= 1)
#pragma unroll
        for (int p = 0; p < st; p++) {
            v[p].x += v[p + st].x;
            v[p].y += v[p + st].y;
            v[p].z += v[p + st].z;
            v[p].w += v[p + st].w;
        }
    float4 o;
    o.x = fmaf(v[0].x, g, xi.x);
    o.y = fmaf(v[0].y, g, xi.y);
    o.z = fmaf(v[0].z, g, xi.z);
    o.w = fmaf(v[0].w, g, xi.w);
    reinterpret_cast<float4*>(out)[i] = o;
}

extern "C" void kernel_launch(void* const* d_in, const int* in_sizes, int n_in,
                              void* d_out, int out_size) {
    const float* x     = (const float*)d_in[0];
    const float* gamma = (const float*)d_in[1];
    float* out = (float*)d_out;

    int b = in_sizes[0] / (NTOK * CDIM);
    if (b < 1) b = 1;
    if (b > MAXB) b = MAXB;
    int nrow = b * NTOK;

    {
        dim3 g(P1BLOCKS, b);
        p1_kernel<<<g, 128>>>(x);
    }
    ky_kernel<<<(nrow + 127) / 128, 128>>>(x, nrow);
    {
        dim3 g(NTOK / 512, ISPLIT2, b);
        p2_kernel<<<g, 256>>>();
    }
    int n4 = nrow * CDIM / 4;
    k3_kernel<<<(n4 + 255) / 256, 256>>>(x, gamma, out, n4);
}